// round 11
// baseline (speedup 1.0000x reference)
#include <cuda_runtime.h>
#include <cuda_bf16.h>

#define DT_F      0.01f
#define DT_D      0.01
#define REG_W     0.01
#define EPS_L     1e-6f
#define LN_MINVAR (-4.6051702f)   // ln(0.01)
#define BATCH     256
#define TLEN      16384
#define NTHR      256             // threads per CTA (8 warps)
#define WARPS_CTA 8
#define STRIPE    1024            // timesteps per warp stripe
#define NCHUNK    16              // chunks per stripe (64 ts each)
#define NSEG      (TLEN/STRIPE)   // 16 stripes per row
#define NGRID     (BATCH*NSEG/WARPS_CTA)  // 512 CTAs
#define NREC      (BATCH*NSEG)    // 4096 per-warp records

// Per-stripe records, [seg][row] so tail reads coalesced.
// recA = (sum_vel.x, sum_vel.y, sum_a.x, sum_a.y)
// recB = (sum_a2, lve, lcs, rgs)
__device__ float4 g_recA[NREC];
__device__ float4 g_recB[NREC];
__device__ int    g_cnt = 0;      // self-resetting completion counter

__global__ __launch_bounds__(NTHR)
void mtl_fused_kernel(const float4* __restrict__ vel4,
                      const float4* __restrict__ cov4,
                      const float4* __restrict__ vgt4,
                      const float4* __restrict__ pgt4,
                      const float2* __restrict__ vel2,
                      const float*  __restrict__ log_dv_p,
                      const float*  __restrict__ log_dc_p,
                      float* __restrict__ out)
{
    __shared__ double dred[WARPS_CTA][4];
    __shared__ int    s_last;

    const int tid  = threadIdx.x;
    const int lane = tid & 31;
    const int wid  = tid >> 5;

    // CTA c: row = c & 255; CTAs 0..255 cover stripes 0..7, 256..511 stripes 8..15
    const int row = blockIdx.x & (BATCH - 1);
    const int sp  = (blockIdx.x >> 8) * WARPS_CTA + wid;    // stripe id 0..15

    // float4 index of this lane's first ts-pair in chunk 0
    long f4 = ((long)row * TLEN + (long)sp * STRIPE) / 2 + lane;

    const float2 v0  = vel2[(long)row * TLEN];              // broadcast (L1)
    const float dv0x = DT_F * v0.x;
    const float dv0y = DT_F * v0.y;

    // ---- prefetch chunk 0 ----
    float4 nv = vel4[f4];
    float4 nc = cov4[f4];
    float4 ng = vgt4[f4];
    float4 np = pgt4[f4];

    float carx = 0.f, cary = 0.f;                           // stripe-local prefix carry
    float sax = 0.f, say = 0.f, sa2 = 0.f;
    float lve = 0.f, lcs = 0.f, rgs = 0.f;

    #pragma unroll 1
    for (int ch = 0; ch < NCHUNK; ++ch) {
        const float4 v = nv, c4 = nc, g = ng, p = np;

        // issue next chunk's loads FIRST (overlap with scan+compute)
        f4 += 32;
        if (ch < NCHUNK - 1) {
            nv = vel4[f4];
            nc = cov4[f4];
            ng = vgt4[f4];
            np = pgt4[f4];
        }

        // ---- warp scan of per-thread (2-ts) vel sums ----
        const float tsx = v.x + v.z;
        const float tsy = v.y + v.w;
        float ix = tsx, iy = tsy;
        #pragma unroll
        for (int off = 1; off < 32; off <<= 1) {
            const float nx = __shfl_up_sync(0xffffffffu, ix, off);
            const float ny = __shfl_up_sync(0xffffffffu, iy, off);
            if (lane >= off) { ix += nx; iy += ny; }
        }
        float ex = carx + (ix - tsx);                       // exclusive prefix, ts0
        float ey = cary + (iy - tsy);
        carx += __shfl_sync(0xffffffffu, ix, 31);           // chunk total -> carry
        cary += __shfl_sync(0xffffffffu, iy, 31);

        // ---- timestep 0: (v.x, v.y) ----
        {
            const float ax = fmaf(DT_F, ex, dv0x) - p.x;
            const float ay = fmaf(DT_F, ey, dv0y) - p.y;
            sax += ax; say += ay;
            sa2 = fmaf(ax, ax, fmaf(ay, ay, sa2));
            ex += v.x; ey += v.y;

            const float dvx = v.x - g.x, dvy = v.y - g.y;
            lve = fmaf(dvx, dvx, fmaf(dvy, dvy, lve));

            const float ivx = fminf(__expf(-c4.x), 100.0f);
            const float ivy = fminf(__expf(-c4.y), 100.0f);
            const float u   = EPS_L * ivx * ivy;
            const float logdet = fmaxf(c4.x, LN_MINVAR) + fmaxf(c4.y, LN_MINVAR)
                               + u * (1.0f - 0.5f * u);
            lcs += ivx * dvx * dvx + ivy * dvy * dvy + logdet;
            rgs += ivx + ivy;
        }
        // ---- timestep 1: (v.z, v.w) ----
        {
            const float ax = fmaf(DT_F, ex, dv0x) - p.z;
            const float ay = fmaf(DT_F, ey, dv0y) - p.w;
            sax += ax; say += ay;
            sa2 = fmaf(ax, ax, fmaf(ay, ay, sa2));

            const float dvx = v.z - g.z, dvy = v.w - g.w;
            lve = fmaf(dvx, dvx, fmaf(dvy, dvy, lve));

            const float ivx = fminf(__expf(-c4.z), 100.0f);
            const float ivy = fminf(__expf(-c4.w), 100.0f);
            const float u   = EPS_L * ivx * ivy;
            const float logdet = fmaxf(c4.z, LN_MINVAR) + fmaxf(c4.w, LN_MINVAR)
                               + u * (1.0f - 0.5f * u);
            lcs += ivx * dvx * dvx + ivy * dvy * dvy + logdet;
            rgs += ivx + ivy;
        }
    }

    // ---- warp reduce 6 floats; lane 0 writes the stripe record ----
    float r[6] = {sax, say, sa2, lve, lcs, rgs};
    #pragma unroll
    for (int off = 16; off > 0; off >>= 1) {
        #pragma unroll
        for (int k = 0; k < 6; ++k)
            r[k] += __shfl_down_sync(0xffffffffu, r[k], off);
    }
    if (lane == 0) {
        const int ri = sp * BATCH + row;                    // [seg][row]
        g_recA[ri] = make_float4(carx, cary, r[0], r[1]);   // carx/cary = stripe vel sum
        g_recB[ri] = make_float4(r[2], r[3], r[4], r[5]);
        __threadfence();                                    // records visible pre-counter
    }
    __syncthreads();
    if (tid == 0) {
        const int done = atomicAdd(&g_cnt, 1);
        s_last = (done == NGRID - 1);
    }
    __syncthreads();

    if (!s_last) return;

    // ================= tail: one CTA, fp64 carry recombination =================
    __threadfence();                                        // acquire all records
    {
        double d[4] = {0.0, 0.0, 0.0, 0.0};
        {
            const int myrow = tid;                          // 256 threads = 256 rows
            double cxd = 0.0, cyd = 0.0;
            #pragma unroll 1
            for (int s = 0; s < NSEG; ++s) {
                const float4 ra = g_recA[s * BATCH + myrow];
                const float4 rb = g_recB[s * BATCH + myrow];
                d[0] += (double)rb.x
                      + 2.0 * DT_D * (cxd * (double)ra.z + cyd * (double)ra.w)
                      + (double)STRIPE * DT_D * DT_D * (cxd * cxd + cyd * cyd);
                d[1] += (double)rb.y;
                d[2] += (double)rb.z;
                d[3] += (double)rb.w;
                cxd += (double)ra.x;
                cyd += (double)ra.y;
            }
        }

        #pragma unroll
        for (int off = 16; off > 0; off >>= 1) {
            #pragma unroll
            for (int k = 0; k < 4; ++k)
                d[k] += __shfl_down_sync(0xffffffffu, d[k], off);
        }
        if (lane == 0) {
            #pragma unroll
            for (int k = 0; k < 4; ++k) dred[wid][k] = d[k];
        }
        __syncthreads();
        if (tid == 0) {
            #pragma unroll
            for (int k = 0; k < 4; ++k) {
                double s = dred[0][k];
                #pragma unroll
                for (int w = 1; w < WARPS_CTA; ++w) s += dred[w][k];
                d[k] = s;
            }
            const double n_all = (double)BATCH * (double)TLEN * 2.0;
            const double n_bt  = (double)BATCH * (double)TLEN;
            const float  ldv = *log_dv_p;
            const float  ldc = *log_dc_p;
            const double dv  = exp((double)ldv);
            const double dc  = exp((double)ldc);

            const double lv_total = (d[0] + d[1]) / n_all;
            const double lc_total = 0.5 * (d[2] / n_bt);
            const double reg      = d[3] / n_bt;

            double total = lv_total / (2.0 * dv * dv)
                         + lc_total / (2.0 * dc * dc)
                         + (double)ldv + (double)ldc
                         + REG_W * reg;
            *out = (float)total;
            g_cnt = 0;                                      // reset for graph replay
        }
    }
}

extern "C" void kernel_launch(void* const* d_in, const int* in_sizes, int n_in,
                              void* d_out, int out_size)
{
    const float4* vel4 = (const float4*)d_in[0];
    const float4* cov4 = (const float4*)d_in[1];
    const float4* vgt4 = (const float4*)d_in[2];
    const float4* pgt4 = (const float4*)d_in[3];
    const float2* vel2 = (const float2*)d_in[0];
    const float*  ldv  = (const float*)d_in[4];
    const float*  ldc  = (const float*)d_in[5];
    float* out = (float*)d_out;

    mtl_fused_kernel<<<NGRID, NTHR>>>(vel4, cov4, vgt4, pgt4, vel2, ldv, ldc, out);
}

// round 12
// speedup vs baseline: 1.0081x; 1.0081x over previous
#include <cuda_runtime.h>
#include <cuda_bf16.h>

#define DT_F      0.01f
#define DT_D      0.01
#define REG_W     0.01
#define EPS_L     1e-6f
#define LN_MINVAR (-4.6051702f)   // ln(0.01)
#define BATCH     256
#define TLEN      16384
#define NTHR      256             // threads per CTA (8 warps)
#define WARPS_CTA 8
#define STRIPE    1024            // timesteps per warp stripe
#define NCHUNK    16              // chunks per stripe (64 ts each)
#define NSEG      (TLEN/STRIPE)   // 16 stripes per row
#define NGRID     (BATCH*NSEG/WARPS_CTA)  // 512 CTAs
#define NREC      (BATCH*NSEG)    // 4096 per-warp records

// Per-stripe records, [seg][row] so tail reads coalesced.
// recA = (sum_vel.x, sum_vel.y, sum_a.x, sum_a.y)
// recB = (sum_a2, lve, lcs, rgs)
__device__ float4 g_recA[NREC];
__device__ float4 g_recB[NREC];
__device__ int    g_cnt = 0;      // self-resetting completion counter

__global__ __launch_bounds__(NTHR)
void mtl_fused_kernel(const float4* __restrict__ vel4,
                      const float4* __restrict__ cov4,
                      const float4* __restrict__ vgt4,
                      const float4* __restrict__ pgt4,
                      const float2* __restrict__ vel2,
                      const float*  __restrict__ log_dv_p,
                      const float*  __restrict__ log_dc_p,
                      float* __restrict__ out)
{
    __shared__ double dred[WARPS_CTA][4];
    __shared__ int    s_last;

    const int tid  = threadIdx.x;
    const int lane = tid & 31;
    const int wid  = tid >> 5;

    // CTA c: row = c & 255; CTAs 0..255 cover stripes 0..7, 256..511 stripes 8..15
    const int row = blockIdx.x & (BATCH - 1);
    const int sp  = (blockIdx.x >> 8) * WARPS_CTA + wid;    // stripe id 0..15

    // float4 index of this lane's first ts-pair in chunk 0
    long f4 = ((long)row * TLEN + (long)sp * STRIPE) / 2 + lane;

    const float2 v0  = vel2[(long)row * TLEN];              // broadcast (L1)
    const float dv0x = DT_F * v0.x;
    const float dv0y = DT_F * v0.y;

    // ---- prefetch chunk 0 ----
    float4 nv = vel4[f4];
    float4 nc = cov4[f4];
    float4 ng = vgt4[f4];
    float4 np = pgt4[f4];

    float carx = 0.f, cary = 0.f;                           // stripe-local prefix carry
    float sax = 0.f, say = 0.f, sa2 = 0.f;
    float lve = 0.f, lcs = 0.f, rgs = 0.f;

    #pragma unroll 1
    for (int ch = 0; ch < NCHUNK; ++ch) {
        const float4 v = nv, c4 = nc, g = ng, p = np;

        // issue next chunk's loads FIRST (overlap with scan+compute)
        f4 += 32;
        if (ch < NCHUNK - 1) {
            nv = vel4[f4];
            nc = cov4[f4];
            ng = vgt4[f4];
            np = pgt4[f4];
        }

        // ---- warp scan of per-thread (2-ts) vel sums ----
        const float tsx = v.x + v.z;
        const float tsy = v.y + v.w;
        float ix = tsx, iy = tsy;
        #pragma unroll
        for (int off = 1; off < 32; off <<= 1) {
            const float nx = __shfl_up_sync(0xffffffffu, ix, off);
            const float ny = __shfl_up_sync(0xffffffffu, iy, off);
            if (lane >= off) { ix += nx; iy += ny; }
        }
        float ex = carx + (ix - tsx);                       // exclusive prefix, ts0
        float ey = cary + (iy - tsy);
        carx += __shfl_sync(0xffffffffu, ix, 31);           // chunk total -> carry
        cary += __shfl_sync(0xffffffffu, iy, 31);

        // ---- timestep 0: (v.x, v.y) ----
        {
            const float ax = fmaf(DT_F, ex, dv0x) - p.x;
            const float ay = fmaf(DT_F, ey, dv0y) - p.y;
            sax += ax; say += ay;
            sa2 = fmaf(ax, ax, fmaf(ay, ay, sa2));
            ex += v.x; ey += v.y;

            const float dvx = v.x - g.x, dvy = v.y - g.y;
            lve = fmaf(dvx, dvx, fmaf(dvy, dvy, lve));

            const float ivx = fminf(__expf(-c4.x), 100.0f);
            const float ivy = fminf(__expf(-c4.y), 100.0f);
            const float u   = EPS_L * ivx * ivy;
            const float logdet = fmaxf(c4.x, LN_MINVAR) + fmaxf(c4.y, LN_MINVAR)
                               + u * (1.0f - 0.5f * u);
            lcs += ivx * dvx * dvx + ivy * dvy * dvy + logdet;
            rgs += ivx + ivy;
        }
        // ---- timestep 1: (v.z, v.w) ----
        {
            const float ax = fmaf(DT_F, ex, dv0x) - p.z;
            const float ay = fmaf(DT_F, ey, dv0y) - p.w;
            sax += ax; say += ay;
            sa2 = fmaf(ax, ax, fmaf(ay, ay, sa2));

            const float dvx = v.z - g.z, dvy = v.w - g.w;
            lve = fmaf(dvx, dvx, fmaf(dvy, dvy, lve));

            const float ivx = fminf(__expf(-c4.z), 100.0f);
            const float ivy = fminf(__expf(-c4.w), 100.0f);
            const float u   = EPS_L * ivx * ivy;
            const float logdet = fmaxf(c4.z, LN_MINVAR) + fmaxf(c4.w, LN_MINVAR)
                               + u * (1.0f - 0.5f * u);
            lcs += ivx * dvx * dvx + ivy * dvy * dvy + logdet;
            rgs += ivx + ivy;
        }
    }

    // ---- warp reduce 6 floats; lane 0 writes the stripe record ----
    float r[6] = {sax, say, sa2, lve, lcs, rgs};
    #pragma unroll
    for (int off = 16; off > 0; off >>= 1) {
        #pragma unroll
        for (int k = 0; k < 6; ++k)
            r[k] += __shfl_down_sync(0xffffffffu, r[k], off);
    }
    if (lane == 0) {
        const int ri = sp * BATCH + row;                    // [seg][row]
        g_recA[ri] = make_float4(carx, cary, r[0], r[1]);   // carx/cary = stripe vel sum
        g_recB[ri] = make_float4(r[2], r[3], r[4], r[5]);
        __threadfence();                                    // records visible pre-counter
    }
    __syncthreads();
    if (tid == 0) {
        const int done = atomicAdd(&g_cnt, 1);
        s_last = (done == NGRID - 1);
    }
    __syncthreads();

    if (!s_last) return;

    // ================= tail: one CTA, fp64 carry recombination =================
    __threadfence();                                        // acquire all records
    {
        double d[4] = {0.0, 0.0, 0.0, 0.0};
        {
            const int myrow = tid;                          // 256 threads = 256 rows
            double cxd = 0.0, cyd = 0.0;
            #pragma unroll 1
            for (int s = 0; s < NSEG; ++s) {
                const float4 ra = g_recA[s * BATCH + myrow];
                const float4 rb = g_recB[s * BATCH + myrow];
                d[0] += (double)rb.x
                      + 2.0 * DT_D * (cxd * (double)ra.z + cyd * (double)ra.w)
                      + (double)STRIPE * DT_D * DT_D * (cxd * cxd + cyd * cyd);
                d[1] += (double)rb.y;
                d[2] += (double)rb.z;
                d[3] += (double)rb.w;
                cxd += (double)ra.x;
                cyd += (double)ra.y;
            }
        }

        #pragma unroll
        for (int off = 16; off > 0; off >>= 1) {
            #pragma unroll
            for (int k = 0; k < 4; ++k)
                d[k] += __shfl_down_sync(0xffffffffu, d[k], off);
        }
        if (lane == 0) {
            #pragma unroll
            for (int k = 0; k < 4; ++k) dred[wid][k] = d[k];
        }
        __syncthreads();
        if (tid == 0) {
            #pragma unroll
            for (int k = 0; k < 4; ++k) {
                double s = dred[0][k];
                #pragma unroll
                for (int w = 1; w < WARPS_CTA; ++w) s += dred[w][k];
                d[k] = s;
            }
            const double n_all = (double)BATCH * (double)TLEN * 2.0;
            const double n_bt  = (double)BATCH * (double)TLEN;
            const float  ldv = *log_dv_p;
            const float  ldc = *log_dc_p;
            const double dv  = exp((double)ldv);
            const double dc  = exp((double)ldc);

            const double lv_total = (d[0] + d[1]) / n_all;
            const double lc_total = 0.5 * (d[2] / n_bt);
            const double reg      = d[3] / n_bt;

            double total = lv_total / (2.0 * dv * dv)
                         + lc_total / (2.0 * dc * dc)
                         + (double)ldv + (double)ldc
                         + REG_W * reg;
            *out = (float)total;
            g_cnt = 0;                                      // reset for graph replay
        }
    }
}

extern "C" void kernel_launch(void* const* d_in, const int* in_sizes, int n_in,
                              void* d_out, int out_size)
{
    const float4* vel4 = (const float4*)d_in[0];
    const float4* cov4 = (const float4*)d_in[1];
    const float4* vgt4 = (const float4*)d_in[2];
    const float4* pgt4 = (const float4*)d_in[3];
    const float2* vel2 = (const float2*)d_in[0];
    const float*  ldv  = (const float*)d_in[4];
    const float*  ldc  = (const float*)d_in[5];
    float* out = (float*)d_out;

    mtl_fused_kernel<<<NGRID, NTHR>>>(vel4, cov4, vgt4, pgt4, vel2, ldv, ldc, out);
}

// round 13
// speedup vs baseline: 1.4179x; 1.4065x over previous
#include <cuda_runtime.h>
#include <cuda_bf16.h>

#define DT_F      0.01f
#define DT_D      0.01
#define REG_W     0.01
#define EPS_L     1e-6f
#define LN_MINVAR (-4.6051702f)   // ln(0.01)
#define BATCH     256
#define TLEN      16384
#define NTHR      256             // threads per CTA (8 warps)
#define NWARP     8
#define NCHUNK    8               // chunks per CTA
#define CHUNK_TS  (NTHR*2)        // 512 timesteps per chunk (2 ts per thread)
#define SEG       (NCHUNK*CHUNK_TS) // 4096 timesteps per CTA segment
#define NSEG      (TLEN/SEG)      // 4 segments per row
#define NGRID     (BATCH*NSEG)    // 1024 CTAs
#define NREC      (BATCH*NSEG)    // 1024 records

// Per-segment records, [seg][row] so pass-2 reads coalesced.
// recA = (sum_vel.x, sum_vel.y, sum_a.x, sum_a.y)
// recB = (sum_a2, lve, lcs, rgs)
__device__ float4 g_recA[NREC];
__device__ float4 g_recB[NREC];

// ================= pass 1: streaming workers, NO fences/atomics =================
__global__ __launch_bounds__(NTHR)
void mtl_pass1_kernel(const float4* __restrict__ vel4,
                      const float4* __restrict__ cov4,
                      const float4* __restrict__ vgt4,
                      const float4* __restrict__ pgt4,
                      const float2* __restrict__ vel2)
{
    __shared__ float2 wsum[NWARP];        // raw warp totals
    __shared__ float2 wpre[NWARP];        // inclusive-scanned warp totals
    __shared__ float  sred[NWARP][6];

    const int tid  = threadIdx.x;
    const int lane = tid & 31;
    const int wid  = tid >> 5;
    const int row  = blockIdx.x & (BATCH - 1);
    const int q    = blockIdx.x >> 8;     // segment 0..3

    const int base_f4 = (row * TLEN + q * SEG) >> 1;   // float4 index of segment start

    const float2 v0  = vel2[row * TLEN];  // broadcast
    const float dv0x = DT_F * v0.x;
    const float dv0y = DT_F * v0.y;

    float carx = 0.f, cary = 0.f;         // segment-local prefix carry
    float sax = 0.f, say = 0.f, sa2 = 0.f;
    float lve = 0.f, lcs = 0.f, rgs = 0.f;

    #pragma unroll 1
    for (int ch = 0; ch < NCHUNK; ++ch) {
        const int f4 = base_f4 + (ch * CHUNK_TS >> 1) + tid;

        const float4 v  = vel4[f4];
        const float4 c4 = cov4[f4];
        const float4 g  = vgt4[f4];
        const float4 p  = pgt4[f4];

        // ---- warp scan of per-thread (2 ts) vel sums ----
        const float tsx = v.x + v.z;
        const float tsy = v.y + v.w;
        float ix = tsx, iy = tsy;
        #pragma unroll
        for (int off = 1; off < 32; off <<= 1) {
            const float nx = __shfl_up_sync(0xffffffffu, ix, off);
            const float ny = __shfl_up_sync(0xffffffffu, iy, off);
            if (lane >= off) { ix += nx; iy += ny; }
        }
        if (lane == 31) wsum[wid] = make_float2(ix, iy);
        __syncthreads();                  // barrier 1: wsum visible

        // warp 0 lanes 0..7 scan the 8 warp totals into wpre
        if (tid < NWARP) {
            float sx = wsum[tid].x, sy = wsum[tid].y;
            #pragma unroll
            for (int off = 1; off < NWARP; off <<= 1) {
                const float nx = __shfl_up_sync(0xffu, sx, off);
                const float ny = __shfl_up_sync(0xffu, sy, off);
                if (tid >= off) { sx += nx; sy += ny; }
            }
            wpre[tid] = make_float2(sx, sy);
        }
        __syncthreads();                  // barrier 2: wpre visible
        // Hazard note: next chunk's writes to wsum happen only after all warps
        // pass this barrier (readers of wsum finished before it); wpre reads
        // below complete before any warp reaches next chunk's barrier 1, which
        // gates the next wpre writes. Two barriers suffice, no double buffer.

        float ex = carx + (ix - tsx);
        float ey = cary + (iy - tsy);
        if (wid > 0) { ex += wpre[wid - 1].x; ey += wpre[wid - 1].y; }
        carx += wpre[NWARP - 1].x;
        cary += wpre[NWARP - 1].y;

        // ---- timestep 0: (v.x, v.y) ----
        {
            const float ax = fmaf(DT_F, ex, dv0x) - p.x;
            const float ay = fmaf(DT_F, ey, dv0y) - p.y;
            sax += ax; say += ay;
            sa2 = fmaf(ax, ax, fmaf(ay, ay, sa2));
            ex += v.x; ey += v.y;

            const float dvx = v.x - g.x, dvy = v.y - g.y;
            lve = fmaf(dvx, dvx, fmaf(dvy, dvy, lve));

            const float ivx = fminf(__expf(-c4.x), 100.0f);
            const float ivy = fminf(__expf(-c4.y), 100.0f);
            const float u   = EPS_L * ivx * ivy;
            const float logdet = fmaxf(c4.x, LN_MINVAR) + fmaxf(c4.y, LN_MINVAR)
                               + u * (1.0f - 0.5f * u);
            lcs += ivx * dvx * dvx + ivy * dvy * dvy + logdet;
            rgs += ivx + ivy;
        }
        // ---- timestep 1: (v.z, v.w) ----
        {
            const float ax = fmaf(DT_F, ex, dv0x) - p.z;
            const float ay = fmaf(DT_F, ey, dv0y) - p.w;
            sax += ax; say += ay;
            sa2 = fmaf(ax, ax, fmaf(ay, ay, sa2));

            const float dvx = v.z - g.z, dvy = v.w - g.w;
            lve = fmaf(dvx, dvx, fmaf(dvy, dvy, lve));

            const float ivx = fminf(__expf(-c4.z), 100.0f);
            const float ivy = fminf(__expf(-c4.w), 100.0f);
            const float u   = EPS_L * ivx * ivy;
            const float logdet = fmaxf(c4.z, LN_MINVAR) + fmaxf(c4.w, LN_MINVAR)
                               + u * (1.0f - 0.5f * u);
            lcs += ivx * dvx * dvx + ivy * dvy * dvy + logdet;
            rgs += ivx + ivy;
        }
    }

    // ---- block reduce 6 floats, thread 0 writes the segment record ----
    float r[6] = {sax, say, sa2, lve, lcs, rgs};
    #pragma unroll
    for (int off = 16; off > 0; off >>= 1) {
        #pragma unroll
        for (int k = 0; k < 6; ++k)
            r[k] += __shfl_down_sync(0xffffffffu, r[k], off);
    }
    if (lane == 0) {
        #pragma unroll
        for (int k = 0; k < 6; ++k) sred[wid][k] = r[k];
    }
    __syncthreads();
    if (tid == 0) {
        #pragma unroll
        for (int k = 0; k < 6; ++k) {
            float s = sred[0][k];
            #pragma unroll
            for (int w = 1; w < NWARP; ++w) s += sred[w][k];
            r[k] = s;
        }
        const int ri = q * BATCH + row;                  // [seg][row]
        g_recA[ri] = make_float4(carx, cary, r[0], r[1]); // carx/cary = segment vel sum
        g_recB[ri] = make_float4(r[2], r[3], r[4], r[5]);
    }
    // plain exit — kernel boundary orders the record stores before pass 2
}

// ================= pass 2: fp64 carry recombination (1 CTA) =================
__global__ __launch_bounds__(NTHR)
void mtl_pass2_kernel(const float*  __restrict__ log_dv_p,
                      const float*  __restrict__ log_dc_p,
                      float* __restrict__ out)
{
    __shared__ double dred[NWARP][4];

    const int tid  = threadIdx.x;
    const int lane = tid & 31;
    const int wid  = tid >> 5;

    double d[4] = {0.0, 0.0, 0.0, 0.0};
    {
        const int myrow = tid;                           // 256 threads = 256 rows
        double cxd = 0.0, cyd = 0.0;
        #pragma unroll
        for (int s = 0; s < NSEG; ++s) {
            const float4 ra = g_recA[s * BATCH + myrow]; // coalesced
            const float4 rb = g_recB[s * BATCH + myrow];
            d[0] += (double)rb.x
                  + 2.0 * DT_D * (cxd * (double)ra.z + cyd * (double)ra.w)
                  + (double)SEG * DT_D * DT_D * (cxd * cxd + cyd * cyd);
            d[1] += (double)rb.y;
            d[2] += (double)rb.z;
            d[3] += (double)rb.w;
            cxd += (double)ra.x;
            cyd += (double)ra.y;
        }
    }

    #pragma unroll
    for (int off = 16; off > 0; off >>= 1) {
        #pragma unroll
        for (int k = 0; k < 4; ++k)
            d[k] += __shfl_down_sync(0xffffffffu, d[k], off);
    }
    if (lane == 0) {
        #pragma unroll
        for (int k = 0; k < 4; ++k) dred[wid][k] = d[k];
    }
    __syncthreads();
    if (tid == 0) {
        #pragma unroll
        for (int k = 0; k < 4; ++k) {
            double s = dred[0][k];
            #pragma unroll
            for (int w = 1; w < NWARP; ++w) s += dred[w][k];
            d[k] = s;
        }
        const double n_all = (double)BATCH * (double)TLEN * 2.0;
        const double n_bt  = (double)BATCH * (double)TLEN;
        const float  ldv = *log_dv_p;
        const float  ldc = *log_dc_p;
        const double dv  = exp((double)ldv);
        const double dc  = exp((double)ldc);

        const double lv_total = (d[0] + d[1]) / n_all;
        const double lc_total = 0.5 * (d[2] / n_bt);
        const double reg      = d[3] / n_bt;

        double total = lv_total / (2.0 * dv * dv)
                     + lc_total / (2.0 * dc * dc)
                     + (double)ldv + (double)ldc
                     + REG_W * reg;
        *out = (float)total;
    }
}

extern "C" void kernel_launch(void* const* d_in, const int* in_sizes, int n_in,
                              void* d_out, int out_size)
{
    const float4* vel4 = (const float4*)d_in[0];
    const float4* cov4 = (const float4*)d_in[1];
    const float4* vgt4 = (const float4*)d_in[2];
    const float4* pgt4 = (const float4*)d_in[3];
    const float2* vel2 = (const float2*)d_in[0];
    const float*  ldv  = (const float*)d_in[4];
    const float*  ldc  = (const float*)d_in[5];
    float* out = (float*)d_out;

    mtl_pass1_kernel<<<NGRID, NTHR>>>(vel4, cov4, vgt4, pgt4, vel2);
    mtl_pass2_kernel<<<1, NTHR>>>(ldv, ldc, out);
}